// round 17
// baseline (speedup 1.0000x reference)
#include <cuda_runtime.h>
#include <cuda_fp16.h>
#include <cstdint>

// ---------------------------------------------------------------------------
// GCN 3-layer: 2-edge/16-lane CSR-gather over fp16 rows + fp16 HMMA GEMM.
// Layer 1: GEMM writes RAW H (no dinv), overlaps degree/CSR pipeline fully;
//          gather1 applies dinv[s]*dinv[d] per edge.
// Layers 2/3: dinv prescaled in GEMM epilogue; gather edges weight 1.
// Gather: warp per node, two edges per step (16 lanes each, LDG.128),
//         channel halves combined via shfl_xor(16) at the end.
// ---------------------------------------------------------------------------

#define MAXN 100000
#define MAXE 1600000
#define SCAN_B 1024
#define FULLM 0xffffffffu

__device__ __align__(16) __half g_h16[MAXN * 128];  // GEMM out
__device__ __align__(16) __half g_a16[MAXN * 128];  // gather out (fp16)
__device__ float g_dinv[MAXN];
__device__ int g_cnt[MAXN];
__device__ int g_fill[MAXN];
__device__ int g_rowptr[MAXN];
__device__ int g_incl[MAXN];
__device__ int g_bsum[256];
__device__ int g_csr[MAXE];
__device__ int g_is64;

__device__ __align__(16) __half g_w1[128 * 128];
__device__ __align__(16) __half g_w2[128 * 128];
__device__ __align__(16) __half g_w3[64 * 128];

static cudaStream_t g_s2;
static cudaEvent_t g_ev_fork, g_ev_join;
static bool g_stream_init = []() {
    cudaStreamCreateWithFlags(&g_s2, cudaStreamNonBlocking);
    cudaEventCreateWithFlags(&g_ev_fork, cudaEventDisableTiming);
    cudaEventCreateWithFlags(&g_ev_join, cudaEventDisableTiming);
    return true;
}();

// ---------------------------------------------------------------------------
// helpers
// ---------------------------------------------------------------------------
__device__ __forceinline__ void mma_f16(float* c, const unsigned* a,
                                        const unsigned* b) {
    asm("mma.sync.aligned.m16n8k16.row.col.f32.f16.f16.f32 "
        "{%0,%1,%2,%3},{%4,%5,%6,%7},{%8,%9},{%0,%1,%2,%3};"
        : "+f"(c[0]), "+f"(c[1]), "+f"(c[2]), "+f"(c[3])
        : "r"(a[0]), "r"(a[1]), "r"(a[2]), "r"(a[3]), "r"(b[0]), "r"(b[1]));
}

__global__ void wconv_all_kernel(const float* __restrict__ W1,
                                 const float* __restrict__ W2,
                                 const float* __restrict__ W3,
                                 __half* __restrict__ w1, __half* __restrict__ w2,
                                 __half* __restrict__ w3) {
    int i = blockIdx.x * blockDim.x + threadIdx.x;
    if (i < 16384) {
        w1[i] = __float2half_rn(W1[i]);
    } else if (i < 32768) {
        int j = i - 16384;
        w2[j] = __float2half_rn(W2[j]);
    } else if (i < 40960) {
        int j = i - 32768;
        w3[j] = __float2half_rn(W3[j]);
    }
}

__global__ void zero_probe_kernel(const unsigned* __restrict__ ei,
                                  int* __restrict__ cnt, int n) {
    int i = blockIdx.x * blockDim.x + threadIdx.x;
    if (blockIdx.x == 0) {
        if (threadIdx.x == 0) g_is64 = 1;
        __syncthreads();
        for (int k = threadIdx.x; k < 1024; k += blockDim.x)
            if (ei[2 * k + 1] != 0) atomicAnd(&g_is64, 0);
    }
    if (i < n) cnt[i] = 0;
}

__device__ __forceinline__ void load_edge(const void* ei, int e, int g, int is64,
                                          int& s, int& d) {
    if (is64) {
        const long long* p = (const long long*)ei;
        s = (int)p[g];
        d = (int)p[e + g];
    } else {
        const int* p = (const int*)ei;
        s = p[g];
        d = p[e + g];
    }
}

// ---------------------------------------------------------------------------
// CSR build
// ---------------------------------------------------------------------------
__global__ void count_kernel(const void* __restrict__ ei, int* __restrict__ cnt,
                             int e, int n) {
    int q = (e + 3) >> 2;
    int t = blockIdx.x * blockDim.x + threadIdx.x;
    if (t >= q) return;
    int is64 = g_is64;
    int d[4];
    int cnt_v = 0;
#pragma unroll
    for (int j = 0; j < 4; j++) {
        int i = t + j * q;
        if (i < e) {
            if (is64) d[cnt_v] = (int)((const long long*)ei)[e + i];
            else      d[cnt_v] = ((const int*)ei)[e + i];
            cnt_v++;
        }
    }
#pragma unroll
    for (int j = 0; j < 4; j++)
        if (j < cnt_v && (unsigned)d[j] < (unsigned)n) atomicAdd(&cnt[d[j]], 1);
}

__global__ void dinv_kernel(const int* __restrict__ cnt, float* __restrict__ dinv,
                            int n) {
    int i = blockIdx.x * blockDim.x + threadIdx.x;
    if (i < n) dinv[i] = rsqrtf((float)cnt[i] + 1.0f);
}

__global__ __launch_bounds__(SCAN_B) void scan_block_kernel(
    const int* __restrict__ cnt, int* __restrict__ incl, int* __restrict__ bsum,
    int n) {
    __shared__ int sm[SCAN_B];
    int i = blockIdx.x * SCAN_B + threadIdx.x;
    int v = (i < n) ? cnt[i] : 0;
    sm[threadIdx.x] = v;
    __syncthreads();
#pragma unroll
    for (int off = 1; off < SCAN_B; off <<= 1) {
        int t = (threadIdx.x >= off) ? sm[threadIdx.x - off] : 0;
        __syncthreads();
        sm[threadIdx.x] += t;
        __syncthreads();
    }
    if (i < n) incl[i] = sm[threadIdx.x];
    if (threadIdx.x == SCAN_B - 1) bsum[blockIdx.x] = sm[SCAN_B - 1];
}

__global__ __launch_bounds__(256) void scan_bsum_kernel(int* __restrict__ bsum,
                                                        int nb) {
    __shared__ int sm[256];
    int v = (threadIdx.x < nb) ? bsum[threadIdx.x] : 0;
    sm[threadIdx.x] = v;
    __syncthreads();
#pragma unroll
    for (int off = 1; off < 256; off <<= 1) {
        int t = (threadIdx.x >= off) ? sm[threadIdx.x - off] : 0;
        __syncthreads();
        sm[threadIdx.x] += t;
        __syncthreads();
    }
    if (threadIdx.x < nb) bsum[threadIdx.x] = sm[threadIdx.x] - v;
}

__global__ void scan_final_kernel(const int* __restrict__ incl,
                                  const int* __restrict__ cnt,
                                  const int* __restrict__ bsum,
                                  int* __restrict__ rowptr,
                                  int* __restrict__ fill, int n) {
    int i = blockIdx.x * blockDim.x + threadIdx.x;
    if (i < n) {
        int rp = incl[i] - cnt[i] + bsum[i / SCAN_B];
        rowptr[i] = rp;
        fill[i] = rp;
    }
}

__global__ void fill_csr_kernel(const void* __restrict__ ei,
                                int* __restrict__ fill, int* __restrict__ csr,
                                int e, int n) {
    int q = (e + 1) >> 1;
    int t = blockIdx.x * blockDim.x + threadIdx.x;
    if (t >= q) return;
    int is64 = g_is64;
    int s[2], d[2];
    int cnt_v = 0;
#pragma unroll
    for (int j = 0; j < 2; j++) {
        int i = t + j * q;
        if (i < e) {
            load_edge(ei, e, i, is64, s[cnt_v], d[cnt_v]);
            cnt_v++;
        }
    }
#pragma unroll
    for (int j = 0; j < 2; j++) {
        if (j < cnt_v && (unsigned)s[j] < (unsigned)n &&
            (unsigned)d[j] < (unsigned)n) {
            int pos = atomicAdd(&fill[d[j]], 1);
            csr[pos] = s[j];
        }
    }
}

// ---------------------------------------------------------------------------
// fp16 HMMA GEMM (single-fp16 W).
// ---------------------------------------------------------------------------
template <int COLS, bool RELU, bool PRESCALE, bool HALFIN>
__global__ __launch_bounds__(256) void gemm_tc_kernel(
    const void* __restrict__ Xv, const __half* __restrict__ W,
    const float* __restrict__ dinv, __half* __restrict__ H, int n) {
    __shared__ __half xs[128][40];
    __shared__ __half ws[COLS][40];

    constexpr int WM = (COLS == 128) ? 2 : 1;
    const int t = threadIdx.x;
    const int wid = t >> 5;
    const int lane = t & 31;
    const int gid = lane >> 2;
    const int tig = lane & 3;
    const int row0 = blockIdx.x * 128;

    int wm0, wn0;
    if (COLS == 128) { wm0 = (wid >> 1) * 32; wn0 = (wid & 1) * 64; }
    else             { wm0 = wid * 16;        wn0 = 0; }

    float acc[WM][8][4];
#pragma unroll
    for (int mt = 0; mt < WM; mt++)
#pragma unroll
        for (int nt = 0; nt < 8; nt++)
#pragma unroll
            for (int i = 0; i < 4; i++) acc[mt][nt][i] = 0.0f;

    for (int kb = 0; kb < 128; kb += 32) {
        if (HALFIN) {
            const unsigned* X2 = (const unsigned*)Xv;
            for (int idx = t; idx < 128 * 16; idx += 256) {
                int r = idx >> 4, kk = idx & 15;
                int row = row0 + r;
                unsigned u = 0;
                if (row < n) {
                    u = X2[row * 64 + (kb >> 1) + kk];
                    if (RELU) {
                        __half2 z = __float2half2_rn(0.0f);
                        __half2 v = *reinterpret_cast<__half2*>(&u);
                        v = __hmax2(v, z);
                        u = *reinterpret_cast<unsigned*>(&v);
                    }
                }
                *reinterpret_cast<unsigned*>(&xs[r][2 * kk]) = u;
            }
        } else {
            const float* X = (const float*)Xv;
            for (int idx = t; idx < 128 * 32; idx += 256) {
                int r = idx >> 5, k = idx & 31;
                int row = row0 + r;
                float v = 0.0f;
                if (row < n) {
                    v = X[row * 128 + kb + k];
                    if (RELU) v = fmaxf(v, 0.0f);
                }
                xs[r][k] = __float2half_rn(v);
            }
        }
        for (int idx = t; idx < COLS * 32; idx += 256) {
            int c = idx >> 5, k = idx & 31;
            ws[c][k] = W[c * 128 + kb + k];
        }
        __syncthreads();

#pragma unroll
        for (int ks = 0; ks < 2; ks++) {
            const int k0 = ks * 16;
            unsigned ax[WM][4];
#pragma unroll
            for (int mt = 0; mt < WM; mt++) {
                int r = wm0 + mt * 16 + gid;
                ax[mt][0] = *reinterpret_cast<const unsigned*>(&xs[r][k0 + tig * 2]);
                ax[mt][1] = *reinterpret_cast<const unsigned*>(&xs[r + 8][k0 + tig * 2]);
                ax[mt][2] = *reinterpret_cast<const unsigned*>(&xs[r][k0 + tig * 2 + 8]);
                ax[mt][3] = *reinterpret_cast<const unsigned*>(&xs[r + 8][k0 + tig * 2 + 8]);
            }
#pragma unroll
            for (int nt = 0; nt < 8; nt++) {
                int c = wn0 + nt * 8 + gid;
                unsigned bw[2];
                bw[0] = *reinterpret_cast<const unsigned*>(&ws[c][k0 + tig * 2]);
                bw[1] = *reinterpret_cast<const unsigned*>(&ws[c][k0 + tig * 2 + 8]);
#pragma unroll
                for (int mt = 0; mt < WM; mt++)
                    mma_f16(acc[mt][nt], ax[mt], bw);
            }
        }
        __syncthreads();
    }

#pragma unroll
    for (int mt = 0; mt < WM; mt++) {
        int r = row0 + wm0 + mt * 16 + gid;
        float d0 = 1.0f, d1 = 1.0f;
        if (PRESCALE) {
            d0 = (r < n) ? dinv[r] : 0.0f;
            d1 = (r + 8 < n) ? dinv[r + 8] : 0.0f;
        }
#pragma unroll
        for (int nt = 0; nt < 8; nt++) {
            int c = wn0 + nt * 8 + tig * 2;
            if (r < n)
                *reinterpret_cast<__half2*>(H + (size_t)r * COLS + c) =
                    __floats2half2_rn(acc[mt][nt][0] * d0, acc[mt][nt][1] * d0);
            if (r + 8 < n)
                *reinterpret_cast<__half2*>(H + (size_t)(r + 8) * COLS + c) =
                    __floats2half2_rn(acc[mt][nt][2] * d1, acc[mt][nt][3] * d1);
        }
    }
}

// ---------------------------------------------------------------------------
// 2-edge/16-lane gathers. Warp per node; lanes split into halves; each half
// handles one edge per step with uint4 loads. WEIGHTED: per-edge w=dinv[s]*dd
// (layer 1, raw H); else w=1 for valid edges (prescaled H).
// acc channel map: lane hl=lane&15 covers channels 8*hl..8*hl+7.
// ---------------------------------------------------------------------------
template <bool WEIGHTED>
__global__ __launch_bounds__(256) void gather128_kernel(
    const int* __restrict__ csr, const int* __restrict__ rowptr,
    const int* __restrict__ cnt, const float* __restrict__ dinv,
    const __half* __restrict__ H, const float* __restrict__ b,
    __half* __restrict__ A, int n) {
    int d = (blockIdx.x * blockDim.x + threadIdx.x) >> 5;
    int lane = threadIdx.x & 31;
    if (d >= n) return;
    const int half = lane >> 4;
    const int hl = lane & 15;
    const int start = rowptr[d];
    const int c = cnt[d];
    const float dd = dinv[d];

    float acc[8];
#pragma unroll
    for (int i = 0; i < 8; i++) acc[i] = 0.0f;

    for (int j0 = 0; j0 < c; j0 += 32) {
        int valid = j0 + lane < c;
        int s = valid ? csr[start + j0 + lane] : 0;
        float ws;
        if (WEIGHTED) ws = valid ? dinv[s] * dd : 0.0f;
        else          ws = valid ? 1.0f : 0.0f;
        int m = min(32, c - j0);
        int steps = (m + 1) >> 1;
#pragma unroll 8
        for (int k = 0; k < steps; k++) {
            int src = 2 * k + half;
            int sk = __shfl_sync(FULLM, s, src);
            float wk = __shfl_sync(FULLM, ws, src);
            uint4 u = reinterpret_cast<const uint4*>(H + (size_t)sk * 128)[hl];
            float2 f0 = __half22float2(*reinterpret_cast<__half2*>(&u.x));
            float2 f1 = __half22float2(*reinterpret_cast<__half2*>(&u.y));
            float2 f2 = __half22float2(*reinterpret_cast<__half2*>(&u.z));
            float2 f3 = __half22float2(*reinterpret_cast<__half2*>(&u.w));
            acc[0] = fmaf(f0.x, wk, acc[0]);
            acc[1] = fmaf(f0.y, wk, acc[1]);
            acc[2] = fmaf(f1.x, wk, acc[2]);
            acc[3] = fmaf(f1.y, wk, acc[3]);
            acc[4] = fmaf(f2.x, wk, acc[4]);
            acc[5] = fmaf(f2.y, wk, acc[5]);
            acc[6] = fmaf(f3.x, wk, acc[6]);
            acc[7] = fmaf(f3.y, wk, acc[7]);
        }
    }
    // combine edge-halves
#pragma unroll
    for (int i = 0; i < 8; i++) acc[i] += __shfl_xor_sync(FULLM, acc[i], 16);

    if (half == 0) {
        // self term
        uint4 u = reinterpret_cast<const uint4*>(H + (size_t)d * 128)[hl];
        float2 f0 = __half22float2(*reinterpret_cast<__half2*>(&u.x));
        float2 f1 = __half22float2(*reinterpret_cast<__half2*>(&u.y));
        float2 f2 = __half22float2(*reinterpret_cast<__half2*>(&u.z));
        float2 f3 = __half22float2(*reinterpret_cast<__half2*>(&u.w));
        float sw = WEIGHTED ? dd * dd : 1.0f;
        acc[0] = fmaf(f0.x, sw, acc[0]);
        acc[1] = fmaf(f0.y, sw, acc[1]);
        acc[2] = fmaf(f1.x, sw, acc[2]);
        acc[3] = fmaf(f1.y, sw, acc[3]);
        acc[4] = fmaf(f2.x, sw, acc[4]);
        acc[5] = fmaf(f2.y, sw, acc[5]);
        acc[6] = fmaf(f3.x, sw, acc[6]);
        acc[7] = fmaf(f3.y, sw, acc[7]);
        const float4 b0 = reinterpret_cast<const float4*>(b)[2 * hl];
        const float4 b1 = reinterpret_cast<const float4*>(b)[2 * hl + 1];
        float scale = WEIGHTED ? 1.0f : dd;  // weighted already carries dd
        float o0 = fmaf(acc[0], scale, b0.x);
        float o1 = fmaf(acc[1], scale, b0.y);
        float o2 = fmaf(acc[2], scale, b0.z);
        float o3 = fmaf(acc[3], scale, b0.w);
        float o4 = fmaf(acc[4], scale, b1.x);
        float o5 = fmaf(acc[5], scale, b1.y);
        float o6 = fmaf(acc[6], scale, b1.z);
        float o7 = fmaf(acc[7], scale, b1.w);
        uint4 o;
        __half2 h0 = __floats2half2_rn(o0, o1);
        __half2 h1 = __floats2half2_rn(o2, o3);
        __half2 h2 = __floats2half2_rn(o4, o5);
        __half2 h3 = __floats2half2_rn(o6, o7);
        o.x = *reinterpret_cast<unsigned*>(&h0);
        o.y = *reinterpret_cast<unsigned*>(&h1);
        o.z = *reinterpret_cast<unsigned*>(&h2);
        o.w = *reinterpret_cast<unsigned*>(&h3);
        reinterpret_cast<uint4*>(A + (size_t)d * 128)[hl] = o;
    }
}

// final gather (64 ch, prescaled H, fp32 out): lane hl covers ch 4hl..4hl+3
__global__ __launch_bounds__(256) void gather64_kernel(
    const int* __restrict__ csr, const int* __restrict__ rowptr,
    const int* __restrict__ cnt, const float* __restrict__ dinv,
    const __half* __restrict__ H, const float* __restrict__ b,
    float* __restrict__ A, int n) {
    int d = (blockIdx.x * blockDim.x + threadIdx.x) >> 5;
    int lane = threadIdx.x & 31;
    if (d >= n) return;
    const int half = lane >> 4;
    const int hl = lane & 15;
    const int start = rowptr[d];
    const int c = cnt[d];
    const float dd = dinv[d];

    float acc[4] = {0.0f, 0.0f, 0.0f, 0.0f};

    for (int j0 = 0; j0 < c; j0 += 32) {
        int valid = j0 + lane < c;
        int s = valid ? csr[start + j0 + lane] : 0;
        float ws = valid ? 1.0f : 0.0f;
        int m = min(32, c - j0);
        int steps = (m + 1) >> 1;
#pragma unroll 8
        for (int k = 0; k < steps; k++) {
            int src = 2 * k + half;
            int sk = __shfl_sync(FULLM, s, src);
            float wk = __shfl_sync(FULLM, ws, src);
            uint2 u = reinterpret_cast<const uint2*>(H + (size_t)sk * 64)[hl];
            float2 f0 = __half22float2(*reinterpret_cast<__half2*>(&u.x));
            float2 f1 = __half22float2(*reinterpret_cast<__half2*>(&u.y));
            acc[0] = fmaf(f0.x, wk, acc[0]);
            acc[1] = fmaf(f0.y, wk, acc[1]);
            acc[2] = fmaf(f1.x, wk, acc[2]);
            acc[3] = fmaf(f1.y, wk, acc[3]);
        }
    }
#pragma unroll
    for (int i = 0; i < 4; i++) acc[i] += __shfl_xor_sync(FULLM, acc[i], 16);

    if (half == 0) {
        uint2 u = reinterpret_cast<const uint2*>(H + (size_t)d * 64)[hl];
        float2 f0 = __half22float2(*reinterpret_cast<__half2*>(&u.x));
        float2 f1 = __half22float2(*reinterpret_cast<__half2*>(&u.y));
        acc[0] += f0.x; acc[1] += f0.y; acc[2] += f1.x; acc[3] += f1.y;
        const float4 bv = reinterpret_cast<const float4*>(b)[hl];
        float4 o;
        o.x = fmaf(acc[0], dd, bv.x);
        o.y = fmaf(acc[1], dd, bv.y);
        o.z = fmaf(acc[2], dd, bv.z);
        o.w = fmaf(acc[3], dd, bv.w);
        reinterpret_cast<float4*>(A + (size_t)d * 64)[hl] = o;
    }
}

// ---------------------------------------------------------------------------
// launch
// ---------------------------------------------------------------------------
extern "C" void kernel_launch(void* const* d_in, const int* in_sizes, int n_in,
                              void* d_out, int out_size) {
    const float* x = (const float*)d_in[0];
    const void* ei = d_in[1];
    const float* W1 = (const float*)d_in[2];
    const float* b1 = (const float*)d_in[3];
    const float* W2 = (const float*)d_in[4];
    const float* b2 = (const float*)d_in[5];
    const float* W3 = (const float*)d_in[6];
    const float* b3 = (const float*)d_in[7];
    float* out = (float*)d_out;

    const int n = in_sizes[0] / 128;
    const int e = in_sizes[1] / 2;

    __half *h16, *a16, *w1, *w2, *w3;
    float *dinv;
    int *cnt, *fill, *rowptr, *incl, *bsum, *csr;
    cudaGetSymbolAddress((void**)&h16, g_h16);
    cudaGetSymbolAddress((void**)&a16, g_a16);
    cudaGetSymbolAddress((void**)&dinv, g_dinv);
    cudaGetSymbolAddress((void**)&cnt, g_cnt);
    cudaGetSymbolAddress((void**)&fill, g_fill);
    cudaGetSymbolAddress((void**)&rowptr, g_rowptr);
    cudaGetSymbolAddress((void**)&incl, g_incl);
    cudaGetSymbolAddress((void**)&bsum, g_bsum);
    cudaGetSymbolAddress((void**)&csr, g_csr);
    cudaGetSymbolAddress((void**)&w1, g_w1);
    cudaGetSymbolAddress((void**)&w2, g_w2);
    cudaGetSymbolAddress((void**)&w3, g_w3);

    const int T = 256;
    const int nb = (n + SCAN_B - 1) / SCAN_B;
    const int gemm_blocks = (n + 127) / 128;
    const int gather_blocks = (n * 32 + T - 1) / T;

    wconv_all_kernel<<<160, 256>>>(W1, W2, W3, w1, w2, w3);
    cudaEventRecord(g_ev_fork, 0);
    cudaStreamWaitEvent(g_s2, g_ev_fork, 0);

    zero_probe_kernel<<<(n + T - 1) / T, T, 0, g_s2>>>((const unsigned*)ei, cnt, n);
    {
        int q = (e + 3) >> 2;
        count_kernel<<<(q + T - 1) / T, T, 0, g_s2>>>(ei, cnt, e, n);
    }
    dinv_kernel<<<(n + T - 1) / T, T, 0, g_s2>>>(cnt, dinv, n);
    scan_block_kernel<<<nb, SCAN_B, 0, g_s2>>>(cnt, incl, bsum, n);
    scan_bsum_kernel<<<1, 256, 0, g_s2>>>(bsum, nb);
    scan_final_kernel<<<(n + T - 1) / T, T, 0, g_s2>>>(incl, cnt, bsum, rowptr,
                                                       fill, n);
    {
        int q = (e + 1) >> 1;
        fill_csr_kernel<<<(q + T - 1) / T, T, 0, g_s2>>>(ei, fill, csr, e, n);
    }
    cudaEventRecord(g_ev_join, g_s2);

    gemm_tc_kernel<128, false, false, false><<<gemm_blocks, 256>>>(
        x, w1, dinv, h16, n);
    cudaStreamWaitEvent(0, g_ev_join, 0);

    // layer 1: weighted gather (raw H) -> a16
    gather128_kernel<true><<<gather_blocks, T>>>(csr, rowptr, cnt, dinv, h16, b1,
                                                 a16, n);
    // layer 2
    gemm_tc_kernel<128, true, true, true><<<gemm_blocks, 256>>>(
        a16, w2, dinv, h16, n);
    gather128_kernel<false><<<gather_blocks, T>>>(csr, rowptr, cnt, dinv, h16, b2,
                                                  a16, n);
    // layer 3
    gemm_tc_kernel<64, true, true, true><<<gemm_blocks, 256>>>(
        a16, w3, dinv, h16, n);
    gather64_kernel<<<gather_blocks, T>>>(csr, rowptr, cnt, dinv, h16, b3, out, n);
}